// round 4
// baseline (speedup 1.0000x reference)
#include <cuda_runtime.h>
#include <math.h>

// Problem constants (fixed by the reference)
#define NN  50000
#define EE  800000
#define F3  32
#define KK  16

// ---------------- scratch (__device__ globals; no allocs allowed) ----------
__device__ float g_A[NN * 64];     // layer input / output embedding
__device__ float g_B[NN * 64];     // scatter accumulator
__device__ float g_C[NN * 64];     // x@W result
__device__ float g_w[EE];          // per-edge norm = dinv[src]*dinv[dst]
__device__ float g_dinv[NN];
__device__ int   g_deg[NN];
__device__ float g_m[F3];          // column sum of embedding
__device__ float g_ctx[F3];        // tanh context
__device__ float g_pool[2][F3];    // attention-pooled embeddings, both graphs

// ---------------- degree / normalization ----------------------------------
__global__ void deg_init_kernel() {
    int i = blockIdx.x * 256 + threadIdx.x;
    if (i < NN) g_deg[i] = 1;                 // self-loop
}

__global__ void deg_count_kernel(const int* __restrict__ dst) {
    int e = blockIdx.x * 256 + threadIdx.x;
    if (e < EE) atomicAdd(&g_deg[dst[e]], 1);
}

__global__ void dinv_kernel() {
    int i = blockIdx.x * 256 + threadIdx.x;
    if (i < NN) g_dinv[i] = rsqrtf((float)g_deg[i]);
}

__global__ void edgew_kernel(const int* __restrict__ src, const int* __restrict__ dst) {
    int e = blockIdx.x * 256 + threadIdx.x;
    if (e < EE) g_w[e] = g_dinv[src[e]] * g_dinv[dst[e]];
}

// ---------------- dense linear: H = X @ W  (Fin fixed = 64) ----------------
template<int FOUT>
__global__ void gemm64_kernel(const float* __restrict__ X,
                              const float* __restrict__ W,
                              float* __restrict__ H) {
    __shared__ float Ws[64 * FOUT];
    int tid = threadIdx.y * FOUT + threadIdx.x;
    for (int i = tid; i < 64 * FOUT; i += 256) Ws[i] = W[i];
    __syncthreads();

    int row = blockIdx.x * (256 / FOUT) + threadIdx.y;
    if (row >= NN) return;
    const float* x = X + row * 64;
    float acc = 0.f;
#pragma unroll
    for (int k = 0; k < 64; k++)
        acc = fmaf(__ldg(&x[k]), Ws[k * FOUT + threadIdx.x], acc);
    H[row * FOUT + threadIdx.x] = acc;
}

// ---------------- accumulator init with self-loop term ---------------------
template<int F>
__global__ void selfloop_kernel(const float* __restrict__ H, float* __restrict__ Acc) {
    int idx = blockIdx.x * 256 + threadIdx.x;      // float4 index
    if (idx >= NN * F / 4) return;
    int row = idx / (F / 4);
    float d = g_dinv[row];
    float d2 = d * d;
    float4 h = ((const float4*)H)[idx];
    float4 o;
    o.x = h.x * d2; o.y = h.y * d2; o.z = h.z * d2; o.w = h.w * d2;
    ((float4*)Acc)[idx] = o;
}

// ---------------- edge scatter: Acc[dst] += H[src] * w ----------------------
template<int F>
__global__ void scatter_kernel(const float* __restrict__ H, float* __restrict__ Acc,
                               const int* __restrict__ src, const int* __restrict__ dst) {
    int e = blockIdx.x * 256 + threadIdx.x;
    if (e >= EE) return;
    int s = src[e];
    int d = dst[e];
    float w = g_w[e];
    int q = blockIdx.y;                             // which float4 of the row
    float4 h = __ldg((const float4*)(H + s * F) + q);
    float* a = Acc + d * F + q * 4;
    asm volatile("red.global.add.v4.f32 [%0], {%1,%2,%3,%4};"
                 :: "l"(a), "f"(h.x * w), "f"(h.y * w), "f"(h.z * w), "f"(h.w * w)
                 : "memory");
}

// ---------------- bias (+ optional ReLU) -----------------------------------
template<int F, bool RELU>
__global__ void bias_kernel(const float* __restrict__ Acc,
                            const float* __restrict__ b,
                            float* __restrict__ Out) {
    int idx = blockIdx.x * 256 + threadIdx.x;      // float4 index
    if (idx >= NN * F / 4) return;
    int jb = (idx % (F / 4)) * 4;
    float4 v = ((const float4*)Acc)[idx];
    v.x += b[jb + 0]; v.y += b[jb + 1]; v.z += b[jb + 2]; v.w += b[jb + 3];
    if (RELU) {
        v.x = fmaxf(v.x, 0.f); v.y = fmaxf(v.y, 0.f);
        v.z = fmaxf(v.z, 0.f); v.w = fmaxf(v.w, 0.f);
    }
    ((float4*)Out)[idx] = v;
}

// ---------------- attention pooling ----------------------------------------
__global__ void zero_small_kernel(int gi) {
    int t = threadIdx.x;
    if (t < F3) { g_m[t] = 0.f; g_pool[gi][t] = 0.f; }
}

// column sums of A (N x 32) into g_m
__global__ void colsum_kernel(const float* __restrict__ A) {
    __shared__ float sh[8][F3];
    int j = threadIdx.x, ty = threadIdx.y;
    float acc = 0.f;
    for (int r = blockIdx.x * 8 + ty; r < NN; r += gridDim.x * 8)
        acc += A[r * F3 + j];
    sh[ty][j] = acc;
    __syncthreads();
    if (ty == 0) {
        float s = 0.f;
#pragma unroll
        for (int t = 0; t < 8; t++) s += sh[t][j];
        atomicAdd(&g_m[j], s);
    }
}

// ctx = tanh(mean(x) @ W_att)   (mean commutes with the linear map)
__global__ void ctx_kernel(const float* __restrict__ Watt) {
    int j = threadIdx.x;   // 32 threads
    float acc = 0.f;
#pragma unroll
    for (int k = 0; k < F3; k++)
        acc += g_m[k] * (1.0f / NN) * Watt[k * F3 + j];
    g_ctx[j] = tanhf(acc);
}

// pool[j] = sum_i A[i][j] * sigmoid(A[i] . ctx)
__global__ void __launch_bounds__(256) attpool_kernel(const float* __restrict__ A, int gi) {
    __shared__ float sp[F3];
    int tid = threadIdx.x;
    if (tid < F3) sp[tid] = 0.f;
    __syncthreads();

    float ctx[F3];
#pragma unroll
    for (int j = 0; j < F3; j++) ctx[j] = g_ctx[j];

    float acc[F3];
#pragma unroll
    for (int j = 0; j < F3; j++) acc[j] = 0.f;

    for (int r = blockIdx.x * blockDim.x + tid; r < NN; r += gridDim.x * blockDim.x) {
        const float4* row = (const float4*)(A + r * F3);
        float rv[F3];
        float dot = 0.f;
#pragma unroll
        for (int q = 0; q < F3 / 4; q++) {
            float4 v = __ldg(row + q);
            rv[q * 4 + 0] = v.x; rv[q * 4 + 1] = v.y;
            rv[q * 4 + 2] = v.z; rv[q * 4 + 3] = v.w;
            dot = fmaf(v.x, ctx[q * 4 + 0], dot);
            dot = fmaf(v.y, ctx[q * 4 + 1], dot);
            dot = fmaf(v.z, ctx[q * 4 + 2], dot);
            dot = fmaf(v.w, ctx[q * 4 + 3], dot);
        }
        float s = 1.f / (1.f + expf(-dot));
#pragma unroll
        for (int j = 0; j < F3; j++) acc[j] = fmaf(rv[j], s, acc[j]);
    }
#pragma unroll
    for (int j = 0; j < F3; j++) atomicAdd(&sp[j], acc[j]);
    __syncthreads();
    if (tid < F3) atomicAdd(&g_pool[gi][tid], sp[tid]);
}

// ---------------- NTN scoring ----------------------------------------------
__global__ void ntn_kernel(const float* __restrict__ Wtn,
                           const float* __restrict__ Wb,
                           const float* __restrict__ btn,
                           float* __restrict__ out) {
    __shared__ float e1[F3], e2[F3];
    int t = threadIdx.x;   // 64 threads
    if (t < F3)            e1[t] = g_pool[0][t];
    else if (t < 2 * F3)   e2[t - F3] = g_pool[1][t - F3];
    __syncthreads();

    if (t < KK) {
        float sc = 0.f;
        for (int i = 0; i < F3; i++) {
            float a = e1[i];
            for (int j = 0; j < F3; j++)
                sc = fmaf(a * e2[j], Wtn[(i * F3 + j) * KK + t], sc);
        }
        float bl = 0.f;
#pragma unroll
        for (int i = 0; i < F3; i++)
            bl += Wb[t * 64 + i] * e1[i] + Wb[t * 64 + F3 + i] * e2[i];
        float v = sc + bl + btn[t];
        out[t] = v > 0.f ? v : 0.f;
    }
}

// ---------------- driver ----------------------------------------------------
extern "C" void kernel_launch(void* const* d_in, const int* in_sizes, int n_in,
                              void* d_out, int out_size) {
    const float* feats[2] = { (const float*)d_in[0], (const float*)d_in[2] };
    const int*   edges[2] = { (const int*)d_in[1],   (const int*)d_in[3]   };
    const float* W1   = (const float*)d_in[4];
    const float* b1   = (const float*)d_in[5];
    const float* W2   = (const float*)d_in[6];
    const float* b2   = (const float*)d_in[7];
    const float* W3   = (const float*)d_in[8];
    const float* b3   = (const float*)d_in[9];
    const float* Watt = (const float*)d_in[10];
    const float* Wtn  = (const float*)d_in[11];
    const float* Wb   = (const float*)d_in[12];
    const float* btn  = (const float*)d_in[13];
    float* out = (float*)d_out;

    const int nb_node = (NN + 255) / 256;
    const int nb_edge = (EE + 255) / 256;        // 3125

    for (int gi = 0; gi < 2; gi++) {
        const int* src = edges[gi];
        const int* dst = edges[gi] + EE;

        deg_init_kernel<<<nb_node, 256>>>();
        deg_count_kernel<<<nb_edge, 256>>>(dst);
        dinv_kernel<<<nb_node, 256>>>();
        edgew_kernel<<<nb_edge, 256>>>(src, dst);

        // layer 1: 64 -> 64, relu
        gemm64_kernel<64><<<(NN + 3) / 4, dim3(64, 4)>>>(feats[gi], W1, g_C);
        selfloop_kernel<64><<<(NN * 16 + 255) / 256, 256>>>(g_C, g_B);
        scatter_kernel<64><<<dim3(nb_edge, 16), 256>>>(g_C, g_B, src, dst);
        bias_kernel<64, true><<<(NN * 16 + 255) / 256, 256>>>(g_B, b1, g_A);

        // layer 2: 64 -> 64, relu
        gemm64_kernel<64><<<(NN + 3) / 4, dim3(64, 4)>>>(g_A, W2, g_C);
        selfloop_kernel<64><<<(NN * 16 + 255) / 256, 256>>>(g_C, g_B);
        scatter_kernel<64><<<dim3(nb_edge, 16), 256>>>(g_C, g_B, src, dst);
        bias_kernel<64, true><<<(NN * 16 + 255) / 256, 256>>>(g_B, b2, g_A);

        // layer 3: 64 -> 32, no relu
        gemm64_kernel<32><<<(NN + 7) / 8, dim3(32, 8)>>>(g_A, W3, g_C);
        selfloop_kernel<32><<<(NN * 8 + 255) / 256, 256>>>(g_C, g_B);
        scatter_kernel<32><<<dim3(nb_edge, 8), 256>>>(g_C, g_B, src, dst);
        bias_kernel<32, false><<<(NN * 8 + 255) / 256, 256>>>(g_B, b3, g_A);

        // attention pooling
        zero_small_kernel<<<1, 32>>>(gi);
        colsum_kernel<<<128, dim3(32, 8)>>>(g_A);
        ctx_kernel<<<1, 32>>>(Watt);
        attpool_kernel<<<208, 256>>>(g_A, gi);
    }

    ntn_kernel<<<1, 64>>>(Wtn, Wb, btn, out);
}

// round 5
// speedup vs baseline: 7.5581x; 7.5581x over previous
#include <cuda_runtime.h>
#include <math.h>

// Problem constants (fixed by the reference)
#define NN  50000
#define EE  800000
#define F3  32
#define KK  16
#define NB  ((NN + 255) / 256)     // 196 scan blocks

// ---------------- scratch (__device__ globals; no allocs allowed) ----------
__device__ float g_A[NN * 64];      // layer activation (gemm input / agg output)
__device__ float g_C[NN * 64];      // gemm output (agg input)
__device__ int   g_csr_src[EE];     // CSR: source node per edge (grouped by dst)
__device__ float g_csr_w[EE];       // CSR: edge weight dinv[s]*dinv[d]
__device__ int   g_rowptr[NN];      // CSR row start (exclusive scan of edge-degree)
__device__ int   g_deg[NN];         // edge in-degree (self-loop NOT included)
__device__ int   g_cur[NN];         // placement cursor
__device__ int   g_scanTmp[NN];     // block-local inclusive scan
__device__ int   g_bsum[256];       // per-block sums
__device__ int   g_boff[256];       // scanned block offsets
__device__ float g_dinv[NN];
__device__ float g_m[F3];           // column sums
__device__ float g_ctx[F3];         // tanh context
__device__ float g_pool[2][F3];     // pooled embeddings

// ---------------- degree / normalization ----------------------------------
__global__ void deg_init_kernel() {
    int i = blockIdx.x * 256 + threadIdx.x;
    if (i < NN) { g_deg[i] = 0; g_cur[i] = 0; }
}

__global__ void deg_count_kernel(const int* __restrict__ dst) {
    int e = blockIdx.x * 256 + threadIdx.x;
    if (e < EE) atomicAdd(&g_deg[dst[e]], 1);
}

__global__ void dinv_kernel() {
    int i = blockIdx.x * 256 + threadIdx.x;
    if (i < NN) g_dinv[i] = rsqrtf((float)(g_deg[i] + 1));   // +1 self loop
}

// ---------------- 3-kernel exclusive scan of g_deg -> g_rowptr -------------
__global__ void scan1_kernel() {
    __shared__ int sh[256];
    int t = threadIdx.x;
    int i = blockIdx.x * 256 + t;
    int v = (i < NN) ? g_deg[i] : 0;
    sh[t] = v;
    __syncthreads();
#pragma unroll
    for (int off = 1; off < 256; off <<= 1) {
        int x = (t >= off) ? sh[t - off] : 0;
        __syncthreads();
        sh[t] += x;
        __syncthreads();
    }
    if (i < NN) g_scanTmp[i] = sh[t];
    if (t == 255) g_bsum[blockIdx.x] = sh[255];
}

__global__ void scan2_kernel() {
    __shared__ int sh[256];
    int t = threadIdx.x;
    int v = (t < NB) ? g_bsum[t] : 0;
    sh[t] = v;
    __syncthreads();
#pragma unroll
    for (int off = 1; off < 256; off <<= 1) {
        int x = (t >= off) ? sh[t - off] : 0;
        __syncthreads();
        sh[t] += x;
        __syncthreads();
    }
    g_boff[t] = sh[t] - v;           // exclusive
}

__global__ void scan3_kernel() {
    int i = blockIdx.x * 256 + threadIdx.x;
    if (i < NN)
        g_rowptr[i] = g_scanTmp[i] - g_deg[i] + g_boff[blockIdx.x];  // exclusive
}

// ---------------- CSR placement --------------------------------------------
__global__ void place_kernel(const int* __restrict__ src, const int* __restrict__ dst) {
    int e = blockIdx.x * 256 + threadIdx.x;
    if (e >= EE) return;
    int s = src[e];
    int d = dst[e];
    int pos = g_rowptr[d] + atomicAdd(&g_cur[d], 1);
    g_csr_src[pos] = s;
    g_csr_w[pos]   = g_dinv[s] * g_dinv[d];
}

// ---------------- dense linear: H = X @ W (Fin = 64) -----------------------
// block (TX, TY): TX = FOUT/4 column-groups, TY rows; each thread 4 outputs.
template<int FOUT>
__global__ void gemm_kernel(const float* __restrict__ X,
                            const float* __restrict__ W,
                            float* __restrict__ H) {
    constexpr int TX = FOUT / 4;
    constexpr int TY = 256 / TX;
    __shared__ float Ws[64 * FOUT];
    __shared__ float Xs[TY][65];

    int tid = threadIdx.y * TX + threadIdx.x;
    for (int i = tid; i < 64 * FOUT; i += 256) Ws[i] = W[i];

    int r0 = blockIdx.x * TY;
    for (int i = tid; i < TY * 64; i += 256) {
        int r = i >> 6, c = i & 63;
        Xs[r][c] = (r0 + r < NN) ? X[(r0 + r) * 64 + c] : 0.f;
    }
    __syncthreads();

    int row = r0 + threadIdx.y;
    if (row >= NN) return;

    float4 acc = make_float4(0.f, 0.f, 0.f, 0.f);
    const float4* Ws4 = (const float4*)Ws;
#pragma unroll
    for (int k = 0; k < 64; k++) {
        float xv = Xs[threadIdx.y][k];
        float4 wv = Ws4[k * TX + threadIdx.x];
        acc.x = fmaf(xv, wv.x, acc.x);
        acc.y = fmaf(xv, wv.y, acc.y);
        acc.z = fmaf(xv, wv.z, acc.z);
        acc.w = fmaf(xv, wv.w, acc.w);
    }
    ((float4*)(H + row * FOUT))[threadIdx.x] = acc;
}

// ---------------- CSR aggregation: Out[n] = relu(sum + selfloop + bias) ----
// One warp per node. Warp reads each source row fully coalesced.
template<int F, bool RELU>
__global__ void __launch_bounds__(256) agg_kernel(const float* __restrict__ H,
                                                  const float* __restrict__ bias,
                                                  float* __restrict__ Out) {
    int gwarp = (blockIdx.x * 256 + threadIdx.x) >> 5;
    int lane  = threadIdx.x & 31;
    if (gwarp >= NN) return;
    int n = gwarp;

    int start = g_rowptr[n];
    int cnt   = g_deg[n];
    float d   = g_dinv[n];
    float d2  = d * d;

    if (F == 64) {
        float2 acc = __ldg((const float2*)(H + n * 64) + lane);
        acc.x *= d2; acc.y *= d2;
        int i = 0;
        for (; i + 2 <= cnt; i += 2) {
            int   s0 = __ldg(&g_csr_src[start + i]);
            float w0 = __ldg(&g_csr_w[start + i]);
            int   s1 = __ldg(&g_csr_src[start + i + 1]);
            float w1 = __ldg(&g_csr_w[start + i + 1]);
            float2 h0 = __ldg((const float2*)(H + s0 * 64) + lane);
            float2 h1 = __ldg((const float2*)(H + s1 * 64) + lane);
            acc.x = fmaf(w0, h0.x, acc.x); acc.y = fmaf(w0, h0.y, acc.y);
            acc.x = fmaf(w1, h1.x, acc.x); acc.y = fmaf(w1, h1.y, acc.y);
        }
        if (i < cnt) {
            int   s0 = __ldg(&g_csr_src[start + i]);
            float w0 = __ldg(&g_csr_w[start + i]);
            float2 h0 = __ldg((const float2*)(H + s0 * 64) + lane);
            acc.x = fmaf(w0, h0.x, acc.x); acc.y = fmaf(w0, h0.y, acc.y);
        }
        float2 b = __ldg((const float2*)bias + lane);
        acc.x += b.x; acc.y += b.y;
        if (RELU) { acc.x = fmaxf(acc.x, 0.f); acc.y = fmaxf(acc.y, 0.f); }
        ((float2*)(Out + n * 64))[lane] = acc;
    } else {  // F == 32
        float acc = __ldg(H + n * 32 + lane) * d2;
        int i = 0;
        for (; i + 2 <= cnt; i += 2) {
            int   s0 = __ldg(&g_csr_src[start + i]);
            float w0 = __ldg(&g_csr_w[start + i]);
            int   s1 = __ldg(&g_csr_src[start + i + 1]);
            float w1 = __ldg(&g_csr_w[start + i + 1]);
            float h0 = __ldg(H + s0 * 32 + lane);
            float h1 = __ldg(H + s1 * 32 + lane);
            acc = fmaf(w0, h0, acc);
            acc = fmaf(w1, h1, acc);
        }
        if (i < cnt) {
            int   s0 = __ldg(&g_csr_src[start + i]);
            float w0 = __ldg(&g_csr_w[start + i]);
            acc = fmaf(w0, __ldg(H + s0 * 32 + lane), acc);
        }
        acc += __ldg(bias + lane);
        if (RELU) acc = fmaxf(acc, 0.f);
        Out[n * 32 + lane] = acc;
    }
}

// ---------------- attention pooling ----------------------------------------
__global__ void zero_small_kernel(int gi) {
    int t = threadIdx.x;
    if (t < F3) { g_m[t] = 0.f; g_pool[gi][t] = 0.f; }
}

__global__ void colsum_kernel(const float* __restrict__ A) {
    __shared__ float sh[8][F3];
    int j = threadIdx.x, ty = threadIdx.y;
    float acc = 0.f;
    for (int r = blockIdx.x * 8 + ty; r < NN; r += gridDim.x * 8)
        acc += A[r * F3 + j];
    sh[ty][j] = acc;
    __syncthreads();
    if (ty == 0) {
        float s = 0.f;
#pragma unroll
        for (int t = 0; t < 8; t++) s += sh[t][j];
        atomicAdd(&g_m[j], s);
    }
}

__global__ void ctx_kernel(const float* __restrict__ Watt) {
    int j = threadIdx.x;
    float acc = 0.f;
#pragma unroll
    for (int k = 0; k < F3; k++)
        acc += g_m[k] * (1.0f / NN) * Watt[k * F3 + j];
    g_ctx[j] = tanhf(acc);
}

__global__ void __launch_bounds__(256) attpool_kernel(const float* __restrict__ A, int gi) {
    __shared__ float sp[F3];
    int tid = threadIdx.x;
    if (tid < F3) sp[tid] = 0.f;
    __syncthreads();

    float ctx[F3];
#pragma unroll
    for (int j = 0; j < F3; j++) ctx[j] = g_ctx[j];

    float acc[F3];
#pragma unroll
    for (int j = 0; j < F3; j++) acc[j] = 0.f;

    for (int r = blockIdx.x * blockDim.x + tid; r < NN; r += gridDim.x * blockDim.x) {
        const float4* row = (const float4*)(A + r * F3);
        float rv[F3];
        float dot = 0.f;
#pragma unroll
        for (int q = 0; q < F3 / 4; q++) {
            float4 v = __ldg(row + q);
            rv[q * 4 + 0] = v.x; rv[q * 4 + 1] = v.y;
            rv[q * 4 + 2] = v.z; rv[q * 4 + 3] = v.w;
            dot = fmaf(v.x, ctx[q * 4 + 0], dot);
            dot = fmaf(v.y, ctx[q * 4 + 1], dot);
            dot = fmaf(v.z, ctx[q * 4 + 2], dot);
            dot = fmaf(v.w, ctx[q * 4 + 3], dot);
        }
        float s = 1.f / (1.f + expf(-dot));
#pragma unroll
        for (int j = 0; j < F3; j++) acc[j] = fmaf(rv[j], s, acc[j]);
    }
#pragma unroll
    for (int j = 0; j < F3; j++) atomicAdd(&sp[j], acc[j]);
    __syncthreads();
    if (tid < F3) atomicAdd(&g_pool[gi][tid], sp[tid]);
}

// ---------------- NTN scoring ----------------------------------------------
__global__ void ntn_kernel(const float* __restrict__ Wtn,
                           const float* __restrict__ Wb,
                           const float* __restrict__ btn,
                           float* __restrict__ out) {
    __shared__ float e1[F3], e2[F3];
    int t = threadIdx.x;
    if (t < F3)          e1[t] = g_pool[0][t];
    else if (t < 2 * F3) e2[t - F3] = g_pool[1][t - F3];
    __syncthreads();

    if (t < KK) {
        float sc = 0.f;
        for (int i = 0; i < F3; i++) {
            float a = e1[i];
            for (int j = 0; j < F3; j++)
                sc = fmaf(a * e2[j], Wtn[(i * F3 + j) * KK + t], sc);
        }
        float bl = 0.f;
#pragma unroll
        for (int i = 0; i < F3; i++)
            bl += Wb[t * 64 + i] * e1[i] + Wb[t * 64 + F3 + i] * e2[i];
        float v = sc + bl + btn[t];
        out[t] = v > 0.f ? v : 0.f;
    }
}

// ---------------- driver ----------------------------------------------------
extern "C" void kernel_launch(void* const* d_in, const int* in_sizes, int n_in,
                              void* d_out, int out_size) {
    const float* feats[2] = { (const float*)d_in[0], (const float*)d_in[2] };
    const int*   edges[2] = { (const int*)d_in[1],   (const int*)d_in[3]   };
    const float* W1   = (const float*)d_in[4];
    const float* b1   = (const float*)d_in[5];
    const float* W2   = (const float*)d_in[6];
    const float* b2   = (const float*)d_in[7];
    const float* W3   = (const float*)d_in[8];
    const float* b3   = (const float*)d_in[9];
    const float* Watt = (const float*)d_in[10];
    const float* Wtn  = (const float*)d_in[11];
    const float* Wb   = (const float*)d_in[12];
    const float* btn  = (const float*)d_in[13];
    float* out = (float*)d_out;

    const int nb_node = NB;                       // 196
    const int nb_edge = (EE + 255) / 256;         // 3125
    const int nb_agg  = (NN * 32 + 255) / 256;    // 6250 (8 warps/block)

    for (int gi = 0; gi < 2; gi++) {
        const int* src = edges[gi];
        const int* dst = edges[gi] + EE;

        // --- CSR build (reused by all 3 layers) ---
        deg_init_kernel<<<nb_node, 256>>>();
        deg_count_kernel<<<nb_edge, 256>>>(dst);
        dinv_kernel<<<nb_node, 256>>>();
        scan1_kernel<<<nb_node, 256>>>();
        scan2_kernel<<<1, 256>>>();
        scan3_kernel<<<nb_node, 256>>>();
        place_kernel<<<nb_edge, 256>>>(src, dst);

        // --- layer 1: 64 -> 64, relu ---
        gemm_kernel<64><<<(NN + 15) / 16, dim3(16, 16)>>>(feats[gi], W1, g_C);
        agg_kernel<64, true><<<nb_agg, 256>>>(g_C, b1, g_A);

        // --- layer 2: 64 -> 64, relu ---
        gemm_kernel<64><<<(NN + 15) / 16, dim3(16, 16)>>>(g_A, W2, g_C);
        agg_kernel<64, true><<<nb_agg, 256>>>(g_C, b2, g_A);

        // --- layer 3: 64 -> 32, no relu ---
        gemm_kernel<32><<<(NN + 31) / 32, dim3(8, 32)>>>(g_A, W3, g_C);
        agg_kernel<32, false><<<nb_agg, 256>>>(g_C, b3, g_A);

        // --- attention pooling ---
        zero_small_kernel<<<1, 32>>>(gi);
        colsum_kernel<<<128, dim3(32, 8)>>>(g_A);
        ctx_kernel<<<1, 32>>>(Watt);
        attpool_kernel<<<208, 256>>>(g_A, gi);
    }

    ntn_kernel<<<1, 64>>>(Wtn, Wb, btn, out);
}